// round 7
// baseline (speedup 1.0000x reference)
#include <cuda_runtime.h>
#include <stdint.h>

// Bidirectional chamfer distance, B=4, N=M=5000, D=3.
// d2/2 = hq + (hr - q.r). Main kernel computes mn = min_ref (hr - q.r) per
// (query, ref-chunk) with software-pipelined SMEM loads; reduce1 adds hq,
// scales, clamps, and sums. Persistent grid of 148*8 CTAs, 2 items each.

#define B_     4
#define N_     5000
#define S_     58          // ref split
#define CHUNK  87          // ceil(N_/S_); 58*87 = 5046 >= 5000
#define TPB    128
#define QPT    8           // queries per thread
#define QPB    1024        // queries per block item
#define QB     5           // query blocks
#define RPAD   88          // loop trip (even); smem holds RPAD+1 entries
#define NITEMS (QB * 8 * S_)   // 2320
#define GRID   1184            // 148 SMs * 8 CTAs
#define PSTR   60          // padded partial stride (floats, mult of 4)
#define NBLK_B 40
#define TPB_B  256

// Scratch: raw per-chunk mins (hr - q.r), then block sums.
__device__ __align__(16) float g_part[2 * B_ * N_ * PSTR];   // 9.6 MB
__device__ float g_bsums[NBLK_B];

#define LDSV2(lo, hi, addr) \
    asm("ld.shared.v2.u64 {%0, %1}, [%2];" : "=l"(lo), "=l"(hi) : "r"(addr))

__global__ __launch_bounds__(TPB, 8) void chamfer_main(const float* __restrict__ pred,
                                                       const float* __restrict__ gt) {
    __shared__ __align__(32) float smf[(RPAD + 1) * 8];   // 2848 B

    const int bid = blockIdx.x;
    const int tid = threadIdx.x;

    for (int it = bid; it < NITEMS; it += GRID) {
        const int qb  = it / (8 * S_);
        const int rem = it - qb * (8 * S_);
        const int bd  = rem / S_;
        const int s   = rem - bd * S_;
        const int dir = bd >> 2;
        const int b   = bd & 3;

        const float* __restrict__ qbase = (dir == 0 ? pred : gt) + b * N_ * 3;
        const float* __restrict__ rb    = (dir == 0 ? gt : pred) + b * N_ * 3;
        const int r0g = s * CHUNK;

        __syncthreads();   // previous item's smem readers done

        // Fill RPAD+1 entries, duplicated per point: {x,x,y,y,z,z,h,h}.
        for (int r = tid; r < RPAD + 1; r += TPB) {
            const int g = r0g + r;
            float gx, gy, gz, h;
            if (r < CHUNK && g < N_) {
                gx = rb[g * 3 + 0];
                gy = rb[g * 3 + 1];
                gz = rb[g * 3 + 2];
                h  = 0.5f * (gx * gx + gy * gy + gz * gz);
            } else {
                gx = 0.0f; gy = 0.0f; gz = 0.0f; h = 1.0e30f;  // sentinel
            }
            smf[r * 8 + 0] = gx; smf[r * 8 + 1] = gx;
            smf[r * 8 + 2] = gy; smf[r * 8 + 3] = gy;
            smf[r * 8 + 4] = gz; smf[r * 8 + 5] = gz;
            smf[r * 8 + 6] = h;  smf[r * 8 + 7] = h;
        }

        // 8 queries/thread as 4 packed f32x2 pairs (negated coords).
        uint64_t nx2[4], ny2[4], nz2[4];
#pragma unroll
        for (int j = 0; j < 4; ++j) {
            int a = qb * QPB + tid + (2 * j) * TPB;
            int c = a + TPB;
            int ac = a < N_ ? a : N_ - 1;
            int cc = c < N_ ? c : N_ - 1;
            float ax = qbase[ac * 3 + 0], ay = qbase[ac * 3 + 1], az = qbase[ac * 3 + 2];
            float bx = qbase[cc * 3 + 0], by = qbase[cc * 3 + 1], bz = qbase[cc * 3 + 2];
            asm("mov.b64 %0, {%1, %2};" : "=l"(nx2[j]) : "f"(-ax), "f"(-bx));
            asm("mov.b64 %0, {%1, %2};" : "=l"(ny2[j]) : "f"(-ay), "f"(-by));
            asm("mov.b64 %0, {%1, %2};" : "=l"(nz2[j]) : "f"(-az), "f"(-bz));
        }

        __syncthreads();

        uint32_t a = (uint32_t)__cvta_generic_to_shared(smf);

        float mn[QPT];
#pragma unroll
        for (int k = 0; k < QPT; ++k) mn[k] = 1.0e30f;

        // Software-pipelined: loads for entry p+1 issue before computing p.
        uint64_t c0, c1, c2, c3, n0, n1, n2, n3;
        LDSV2(c0, c1, a);
        LDSV2(c2, c3, a + 16);
        for (int p = 0; p < RPAD; p += 2) {
            LDSV2(n0, n1, a + 32);
            LDSV2(n2, n3, a + 48);
#pragma unroll
            for (int j = 0; j < 4; ++j) {
                float u0, u1;
                asm("{\n\t"
                    ".reg .b64 t;\n\t"
                    "fma.rn.f32x2 t, %2, %3, %4;\n\t"
                    "fma.rn.f32x2 t, %5, %6, t;\n\t"
                    "fma.rn.f32x2 t, %7, %8, t;\n\t"
                    "mov.b64 {%0, %1}, t;\n\t"
                    "}"
                    : "=f"(u0), "=f"(u1)
                    : "l"(nz2[j]), "l"(c2), "l"(c3),
                      "l"(ny2[j]), "l"(c1),
                      "l"(nx2[j]), "l"(c0));
                mn[2 * j]     = fminf(mn[2 * j], u0);
                mn[2 * j + 1] = fminf(mn[2 * j + 1], u1);
            }
            LDSV2(c0, c1, a + 64);
            LDSV2(c2, c3, a + 80);
#pragma unroll
            for (int j = 0; j < 4; ++j) {
                float u0, u1;
                asm("{\n\t"
                    ".reg .b64 t;\n\t"
                    "fma.rn.f32x2 t, %2, %3, %4;\n\t"
                    "fma.rn.f32x2 t, %5, %6, t;\n\t"
                    "fma.rn.f32x2 t, %7, %8, t;\n\t"
                    "mov.b64 {%0, %1}, t;\n\t"
                    "}"
                    : "=f"(u0), "=f"(u1)
                    : "l"(nz2[j]), "l"(n2), "l"(n3),
                      "l"(ny2[j]), "l"(n1),
                      "l"(nx2[j]), "l"(n0));
                mn[2 * j]     = fminf(mn[2 * j], u0);
                mn[2 * j + 1] = fminf(mn[2 * j + 1], u1);
            }
            a += 64;
        }

        // Store raw mins (hq added in reduce1). Recompute query indices.
        const int base = (dir * B_ + b) * N_;
#pragma unroll
        for (int k = 0; k < QPT; ++k) {
            int q = qb * QPB + tid + k * TPB;
            if (q < N_) g_part[(base + q) * PSTR + s] = mn[k];
        }
    }
}

__global__ __launch_bounds__(TPB_B) void chamfer_reduce1(const float* __restrict__ pred,
                                                         const float* __restrict__ gt) {
    __shared__ float ssum[TPB_B];
    const int gtid = blockIdx.x * TPB_B + threadIdx.x;
    float acc = 0.0f;
    for (int q = gtid; q < 2 * B_ * N_; q += NBLK_B * TPB_B) {
        const float* row = g_part + q * PSTR;
        const float4* p4 = (const float4*)row;
        float m = 1.0e30f;
#pragma unroll
        for (int i = 0; i < 14; ++i) {   // entries 0..55
            float4 a = p4[i];
            m = fminf(m, fminf(fminf(a.x, a.y), fminf(a.z, a.w)));
        }
        m = fminf(m, fminf(row[56], row[57]));   // entries 56,57 (S_=58)
        // hq for this row's query
        const int dir = q / (B_ * N_);
        const int rb_ = (q - dir * B_ * N_) / N_;
        const int qq  = q - dir * B_ * N_ - rb_ * N_;
        const float* qbase = (dir == 0 ? pred : gt) + rb_ * N_ * 3;
        float x = qbase[qq * 3 + 0], y = qbase[qq * 3 + 1], z = qbase[qq * 3 + 2];
        float hq = 0.5f * (x * x + y * y + z * z);
        acc += fmaxf(2.0f * (hq + m), 0.0f);
    }
    ssum[threadIdx.x] = acc;
    __syncthreads();
    for (int off = TPB_B / 2; off > 0; off >>= 1) {
        if (threadIdx.x < off) ssum[threadIdx.x] += ssum[threadIdx.x + off];
        __syncthreads();
    }
    if (threadIdx.x == 0) g_bsums[blockIdx.x] = ssum[0];
}

__global__ void chamfer_reduce2(float* __restrict__ out) {
    __shared__ float sv[64];
    float v = (threadIdx.x < NBLK_B) ? g_bsums[threadIdx.x] : 0.0f;
    sv[threadIdx.x] = v;
    __syncthreads();
    if (threadIdx.x == 0) {
        float t = 0.0f;
#pragma unroll
        for (int i = 0; i < 64; ++i) t += sv[i];
        out[0] = t * (1.0f / (B_ * N_));
    }
}

extern "C" void kernel_launch(void* const* d_in, const int* in_sizes, int n_in,
                              void* d_out, int out_size) {
    const float* pred = (const float*)d_in[0];
    const float* gt   = (const float*)d_in[1];
    chamfer_main<<<GRID, TPB>>>(pred, gt);
    chamfer_reduce1<<<NBLK_B, TPB_B>>>(pred, gt);
    chamfer_reduce2<<<1, 64>>>((float*)d_out);
}

// round 8
// speedup vs baseline: 1.0733x; 1.0733x over previous
#include <cuda_runtime.h>
#include <stdint.h>

// Bidirectional chamfer distance, B=4, N=M=5000, D=3.
// d2/2 = hq + (hr - q.r). Main kernel: mn = min over a ref chunk of (hr - q.r)
// per query; 10 queries/thread as 5 f32x2 packed pairs; refs broadcast from
// SMEM duplicated {x,x,y,y,z,z,h,h}. reduce1 adds hq, scales, clamps, sums.
// launch_bounds(128,8) pins regs<=64; grid = 4*8*37 = 1184 = 148 SMs x 8 CTAs
// (exactly one wave).

#define B_     4
#define N_     5000
#define S_     37          // ref split
#define CHUNK  136         // ceil(N_/S_); 37*136 = 5032 >= 5000
#define TPB    128
#define QPT    10          // queries per thread (5 f32x2 pairs)
#define QPB    1280        // queries per block
#define QB     4           // query blocks: 4*1280 = 5120 >= 5000
#define PSTR   40          // padded partial stride (floats)
#define NBLK_B 40
#define TPB_B  256

// Scratch: raw per-chunk mins (hr - q.r), then block sums.
__device__ __align__(16) float g_part[2 * B_ * N_ * PSTR];   // 6.4 MB
__device__ float g_bsums[NBLK_B];

__global__ __launch_bounds__(TPB, 8) void chamfer_main(const float* __restrict__ pred,
                                                       const float* __restrict__ gt) {
    __shared__ __align__(32) float smf[CHUNK * 8];   // 4352 B

    const int qb  = blockIdx.x;          // query block 0..QB-1
    const int bd  = blockIdx.y;          // dir*B_ + b, 0..7
    const int s   = blockIdx.z;          // ref split 0..S_-1
    const int dir = bd >> 2;             // 0: pred->gt, 1: gt->pred
    const int b   = bd & 3;

    const float* __restrict__ qbase = (dir == 0 ? pred : gt) + b * N_ * 3;
    const float* __restrict__ rb    = (dir == 0 ? gt : pred) + b * N_ * 3;

    const int tid = threadIdx.x;
    const int r0g = s * CHUNK;

    // Cooperative fill, duplicated per point: {x,x,y,y,z,z,h,h}.
    for (int r = tid; r < CHUNK; r += TPB) {
        const int g = r0g + r;
        float gx, gy, gz, h;
        if (g < N_) {
            gx = rb[g * 3 + 0];
            gy = rb[g * 3 + 1];
            gz = rb[g * 3 + 2];
            h  = 0.5f * (gx * gx + gy * gy + gz * gz);
        } else {
            gx = 0.0f; gy = 0.0f; gz = 0.0f; h = 1.0e30f;  // sentinel
        }
        smf[r * 8 + 0] = gx; smf[r * 8 + 1] = gx;
        smf[r * 8 + 2] = gy; smf[r * 8 + 3] = gy;
        smf[r * 8 + 4] = gz; smf[r * 8 + 5] = gz;
        smf[r * 8 + 6] = h;  smf[r * 8 + 7] = h;
    }

    // 10 queries/thread as 5 packed f32x2 pairs (negated coords).
    uint64_t nx2[5], ny2[5], nz2[5];
#pragma unroll
    for (int j = 0; j < 5; ++j) {
        int a = qb * QPB + tid + (2 * j) * TPB;
        int c = a + TPB;
        int ac = a < N_ ? a : N_ - 1;
        int cc = c < N_ ? c : N_ - 1;
        float ax = qbase[ac * 3 + 0], ay = qbase[ac * 3 + 1], az = qbase[ac * 3 + 2];
        float bx = qbase[cc * 3 + 0], by = qbase[cc * 3 + 1], bz = qbase[cc * 3 + 2];
        asm("mov.b64 %0, {%1, %2};" : "=l"(nx2[j]) : "f"(-ax), "f"(-bx));
        asm("mov.b64 %0, {%1, %2};" : "=l"(ny2[j]) : "f"(-ay), "f"(-by));
        asm("mov.b64 %0, {%1, %2};" : "=l"(nz2[j]) : "f"(-az), "f"(-bz));
    }

    __syncthreads();

    uint32_t sa = (uint32_t)__cvta_generic_to_shared(smf);

    float mn[QPT];
#pragma unroll
    for (int k = 0; k < QPT; ++k) mn[k] = 1.0e30f;

#pragma unroll 2
    for (int p = 0; p < CHUNK; ++p) {
        uint64_t rx, ry, rz, rh;
        uint32_t a = sa + p * 32;
        asm("ld.shared.v2.u64 {%0, %1}, [%2];" : "=l"(rx), "=l"(ry) : "r"(a));
        asm("ld.shared.v2.u64 {%0, %1}, [%2];" : "=l"(rz), "=l"(rh) : "r"(a + 16));
#pragma unroll
        for (int j = 0; j < 5; ++j) {
            float u0, u1;
            asm("{\n\t"
                ".reg .b64 t;\n\t"
                "fma.rn.f32x2 t, %2, %3, %4;\n\t"
                "fma.rn.f32x2 t, %5, %6, t;\n\t"
                "fma.rn.f32x2 t, %7, %8, t;\n\t"
                "mov.b64 {%0, %1}, t;\n\t"
                "}"
                : "=f"(u0), "=f"(u1)
                : "l"(nz2[j]), "l"(rz), "l"(rh),
                  "l"(ny2[j]), "l"(ry),
                  "l"(nx2[j]), "l"(rx));
            mn[2 * j]     = fminf(mn[2 * j], u0);
            mn[2 * j + 1] = fminf(mn[2 * j + 1], u1);
        }
    }

    // Store raw mins; hq added (and clamp/scale applied) in reduce1.
    const int base = (dir * B_ + b) * N_;
#pragma unroll
    for (int k = 0; k < QPT; ++k) {
        int q = qb * QPB + tid + k * TPB;
        if (q < N_) g_part[(base + q) * PSTR + s] = mn[k];
    }
}

__global__ __launch_bounds__(TPB_B) void chamfer_reduce1(const float* __restrict__ pred,
                                                         const float* __restrict__ gt) {
    __shared__ float ssum[TPB_B];
    const int gtid = blockIdx.x * TPB_B + threadIdx.x;
    float acc = 0.0f;
    for (int q = gtid; q < 2 * B_ * N_; q += NBLK_B * TPB_B) {
        const float* row = g_part + q * PSTR;
        const float4* p4 = (const float4*)row;
        float m = 1.0e30f;
#pragma unroll
        for (int i = 0; i < 9; ++i) {    // entries 0..35
            float4 a = p4[i];
            m = fminf(m, fminf(fminf(a.x, a.y), fminf(a.z, a.w)));
        }
        m = fminf(m, row[36]);           // entry 36 (S_=37)
        const int dir = q / (B_ * N_);
        const int rb_ = (q - dir * B_ * N_) / N_;
        const int qq  = q - dir * B_ * N_ - rb_ * N_;
        const float* qbase = (dir == 0 ? pred : gt) + rb_ * N_ * 3;
        float x = qbase[qq * 3 + 0], y = qbase[qq * 3 + 1], z = qbase[qq * 3 + 2];
        float hq = 0.5f * (x * x + y * y + z * z);
        acc += fmaxf(2.0f * (hq + m), 0.0f);
    }
    ssum[threadIdx.x] = acc;
    __syncthreads();
    for (int off = TPB_B / 2; off > 0; off >>= 1) {
        if (threadIdx.x < off) ssum[threadIdx.x] += ssum[threadIdx.x + off];
        __syncthreads();
    }
    if (threadIdx.x == 0) g_bsums[blockIdx.x] = ssum[0];
}

__global__ void chamfer_reduce2(float* __restrict__ out) {
    __shared__ float sv[64];
    float v = (threadIdx.x < NBLK_B) ? g_bsums[threadIdx.x] : 0.0f;
    sv[threadIdx.x] = v;
    __syncthreads();
    if (threadIdx.x == 0) {
        float t = 0.0f;
#pragma unroll
        for (int i = 0; i < 64; ++i) t += sv[i];
        out[0] = t * (1.0f / (B_ * N_));
    }
}

extern "C" void kernel_launch(void* const* d_in, const int* in_sizes, int n_in,
                              void* d_out, int out_size) {
    const float* pred = (const float*)d_in[0];
    const float* gt   = (const float*)d_in[1];
    dim3 grid(QB, 2 * B_, S_);
    chamfer_main<<<grid, TPB>>>(pred, gt);
    chamfer_reduce1<<<NBLK_B, TPB_B>>>(pred, gt);
    chamfer_reduce2<<<1, 64>>>((float*)d_out);
}

// round 9
// speedup vs baseline: 1.0899x; 1.0154x over previous
#include <cuda_runtime.h>
#include <stdint.h>

// Bidirectional chamfer distance, B=4, N=M=5000, D=3.
// d2/2 = hq + hr - q.r. 8 queries/thread as 4 f32x2 packed pairs; refs
// broadcast from SMEM duplicated {x,x,y,y,z,z,h,h} -> ld.shared.v2.u64 gives
// aligned f32x2 operands. fma.rn.f32x2 + scalar FMNMX (R4 champion config).
// Split-K combine via global atomicMin on monotone-encoded floats (exact,
// order-independent -> deterministic), then one tiny single-CTA finish.

#define B_    4
#define N_    5000
#define S_    40         // ref split (split-K over refs)
#define CHUNK 125        // N_/S_
#define TPB   128        // threads per block
#define QPT   8          // queries per thread
#define QPB   1024       // queries per block
#define QB    5          // ceil(5000/1024)
#define RPAD  128        // padded refs per chunk
#define NQTOT (2 * B_ * N_)   // 40000

// Scratch: per-(dir,b,q) running min as monotone-encoded uint.
__device__ __align__(16) unsigned int g_min[NQTOT];

__device__ __forceinline__ unsigned int f2key(float v) {
    unsigned int u = __float_as_uint(v);
    return (u & 0x80000000u) ? ~u : (u ^ 0x80000000u);
}
__device__ __forceinline__ float key2f(unsigned int k) {
    unsigned int u = (k & 0x80000000u) ? (k ^ 0x80000000u) : ~k;
    return __uint_as_float(u);
}

__global__ void chamfer_init() {
    int i = blockIdx.x * blockDim.x + threadIdx.x;
    if (i < NQTOT) g_min[i] = 0xFFFFFFFFu;   // key(+inf-ish): largest key
}

__global__ __launch_bounds__(TPB) void chamfer_main(const float* __restrict__ pred,
                                                    const float* __restrict__ gt) {
    __shared__ __align__(32) float smf[RPAD * 8];   // 4 KB

    const int qb  = blockIdx.x;          // query block 0..QB-1
    const int bd  = blockIdx.y;          // dir*B_ + b, 0..7
    const int s   = blockIdx.z;          // ref split 0..S_-1
    const int dir = bd >> 2;             // 0: pred->gt, 1: gt->pred
    const int b   = bd & 3;

    const float* __restrict__ qbase = (dir == 0 ? pred : gt) + b * N_ * 3;
    const float* __restrict__ rbase = (dir == 0 ? gt : pred) + b * N_ * 3 + s * CHUNK * 3;

    const int tid = threadIdx.x;

    // Cooperative load of the ref chunk, duplicated per point for f32x2 ops.
    for (int r = tid; r < RPAD; r += TPB) {
        float gx, gy, gz, h;
        if (r < CHUNK) {
            gx = rbase[r * 3 + 0];
            gy = rbase[r * 3 + 1];
            gz = rbase[r * 3 + 2];
            h  = 0.5f * (gx * gx + gy * gy + gz * gz);
        } else {
            gx = 0.0f; gy = 0.0f; gz = 0.0f; h = 1.0e30f;  // sentinel
        }
        smf[r * 8 + 0] = gx; smf[r * 8 + 1] = gx;
        smf[r * 8 + 2] = gy; smf[r * 8 + 3] = gy;
        smf[r * 8 + 4] = gz; smf[r * 8 + 5] = gz;
        smf[r * 8 + 6] = h;  smf[r * 8 + 7] = h;
    }

    // 8 queries per thread: q_k = qb*QPB + tid + k*TPB, packed pairs (2j, 2j+1).
    int   qi[QPT];
    float hq[QPT];
    uint64_t nx2[4], ny2[4], nz2[4];
#pragma unroll
    for (int j = 0; j < 4; ++j) {
        int k0 = 2 * j, k1 = 2 * j + 1;
        int a = qb * QPB + tid + k0 * TPB;
        int c = qb * QPB + tid + k1 * TPB;
        qi[k0] = a; qi[k1] = c;
        int ac = a < N_ ? a : N_ - 1;
        int cc = c < N_ ? c : N_ - 1;
        float ax = qbase[ac * 3 + 0], ay = qbase[ac * 3 + 1], az = qbase[ac * 3 + 2];
        float bx = qbase[cc * 3 + 0], by = qbase[cc * 3 + 1], bz = qbase[cc * 3 + 2];
        hq[k0] = 0.5f * (ax * ax + ay * ay + az * az);
        hq[k1] = 0.5f * (bx * bx + by * by + bz * bz);
        asm("mov.b64 %0, {%1, %2};" : "=l"(nx2[j]) : "f"(-ax), "f"(-bx));
        asm("mov.b64 %0, {%1, %2};" : "=l"(ny2[j]) : "f"(-ay), "f"(-by));
        asm("mov.b64 %0, {%1, %2};" : "=l"(nz2[j]) : "f"(-az), "f"(-bz));
    }

    __syncthreads();

    uint32_t sbase = (uint32_t)__cvta_generic_to_shared(smf);

    float mn[QPT];
#pragma unroll
    for (int k = 0; k < QPT; ++k) mn[k] = 1.0e30f;

#pragma unroll 4
    for (int p = 0; p < RPAD; ++p) {
        uint64_t rx, ry, rz, rh;
        uint32_t a = sbase + p * 32;
        asm("ld.shared.v2.u64 {%0, %1}, [%2];" : "=l"(rx), "=l"(ry) : "r"(a));
        asm("ld.shared.v2.u64 {%0, %1}, [%2];" : "=l"(rz), "=l"(rh) : "r"(a + 16));
#pragma unroll
        for (int j = 0; j < 4; ++j) {
            // u = h - q.r for the two packed queries; unpack mov elided by ptxas.
            float u0, u1;
            asm("{\n\t"
                ".reg .b64 t;\n\t"
                "fma.rn.f32x2 t, %2, %3, %4;\n\t"
                "fma.rn.f32x2 t, %5, %6, t;\n\t"
                "fma.rn.f32x2 t, %7, %8, t;\n\t"
                "mov.b64 {%0, %1}, t;\n\t"
                "}"
                : "=f"(u0), "=f"(u1)
                : "l"(nz2[j]), "l"(rz), "l"(rh),
                  "l"(ny2[j]), "l"(ry),
                  "l"(nx2[j]), "l"(rx));
            mn[2 * j]     = fminf(mn[2 * j], u0);
            mn[2 * j + 1] = fminf(mn[2 * j + 1], u1);
        }
    }

    // Combine across ref chunks with exact, order-independent atomicMin.
    const int base = (dir * B_ + b) * N_;
#pragma unroll
    for (int k = 0; k < QPT; ++k) {
        if (qi[k] < N_) {
            float v = 2.0f * (hq[k] + mn[k]);   // unclamped d2 for this chunk
            atomicMin(&g_min[base + qi[k]], f2key(v));
        }
    }
}

__global__ __launch_bounds__(1024) void chamfer_finish(float* __restrict__ out) {
    __shared__ float ssum[1024];
    const int tid = threadIdx.x;
    float acc = 0.0f;
    for (int i = tid; i < NQTOT; i += 1024) {
        float v = key2f(g_min[i]);
        acc += fmaxf(v, 0.0f);
    }
    ssum[tid] = acc;
    __syncthreads();
    for (int off = 512; off > 0; off >>= 1) {
        if (tid < off) ssum[tid] += ssum[tid + off];
        __syncthreads();
    }
    if (tid == 0) out[0] = ssum[0] * (1.0f / (B_ * N_));
}

extern "C" void kernel_launch(void* const* d_in, const int* in_sizes, int n_in,
                              void* d_out, int out_size) {
    const float* pred = (const float*)d_in[0];
    const float* gt   = (const float*)d_in[1];
    chamfer_init<<<(NQTOT + 1023) / 1024, 1024>>>();
    dim3 grid(QB, 2 * B_, S_);
    chamfer_main<<<grid, TPB>>>(pred, gt);
    chamfer_finish<<<1, 1024>>>((float*)d_out);
}

// round 10
// speedup vs baseline: 1.0907x; 1.0007x over previous
#include <cuda_runtime.h>
#include <stdint.h>

// Bidirectional chamfer distance, B=4, N=M=5000, D=3.
// d2/2 = hq + hr - q.r. 8 queries/thread as 4 f32x2 packed pairs; refs
// broadcast from SMEM duplicated {x,x,y,y,z,z,h,h} -> ld.shared.v2.u64 gives
// aligned f32x2 operands. fma.rn.f32x2 + scalar FMNMX (R4 champion config).
// Split-K combine via global atomicMax on COMPLEMENTED monotone float keys:
// identity = 0 == static zero-init of __device__ memory, so no init kernel.
// The finish kernel resets entries to 0 as it consumes them (graph replays
// then also start from the identity). Exact, order-independent, deterministic.

#define B_    4
#define N_    5000
#define S_    40         // ref split (split-K over refs)
#define CHUNK 125        // N_/S_
#define TPB   128        // threads per block
#define QPT   8          // queries per thread
#define QPB   1024       // queries per block
#define QB    5          // ceil(5000/1024)
#define RPAD  128        // padded refs per chunk
#define NQTOT (2 * B_ * N_)   // 40000

// Per-(dir,b,q) running min, encoded so that larger key == smaller value and
// key 0 (static zero-init) is the identity (represents +huge).
__device__ unsigned int g_min[NQTOT];   // zero-initialized by CUDA runtime

// Monotone DEcreasing encode: v smaller -> key larger. key = ~m(v), where
// m(v) is the classic sign-flip order-preserving map.
__device__ __forceinline__ unsigned int f2key(float v) {
    unsigned int u = __float_as_uint(v);
    unsigned int m = (u & 0x80000000u) ? ~u : (u ^ 0x80000000u);
    return ~m;
}
__device__ __forceinline__ float key2f(unsigned int k) {
    unsigned int m = ~k;
    unsigned int u = (m & 0x80000000u) ? (m ^ 0x80000000u) : ~m;
    return __uint_as_float(u);
}

__global__ __launch_bounds__(TPB) void chamfer_main(const float* __restrict__ pred,
                                                    const float* __restrict__ gt) {
    __shared__ __align__(32) float smf[RPAD * 8];   // 4 KB

    const int qb  = blockIdx.x;          // query block 0..QB-1
    const int bd  = blockIdx.y;          // dir*B_ + b, 0..7
    const int s   = blockIdx.z;          // ref split 0..S_-1
    const int dir = bd >> 2;             // 0: pred->gt, 1: gt->pred
    const int b   = bd & 3;

    const float* __restrict__ qbase = (dir == 0 ? pred : gt) + b * N_ * 3;
    const float* __restrict__ rbase = (dir == 0 ? gt : pred) + b * N_ * 3 + s * CHUNK * 3;

    const int tid = threadIdx.x;

    // Cooperative load of the ref chunk, duplicated per point for f32x2 ops.
    for (int r = tid; r < RPAD; r += TPB) {
        float gx, gy, gz, h;
        if (r < CHUNK) {
            gx = rbase[r * 3 + 0];
            gy = rbase[r * 3 + 1];
            gz = rbase[r * 3 + 2];
            h  = 0.5f * (gx * gx + gy * gy + gz * gz);
        } else {
            gx = 0.0f; gy = 0.0f; gz = 0.0f; h = 1.0e30f;  // sentinel
        }
        smf[r * 8 + 0] = gx; smf[r * 8 + 1] = gx;
        smf[r * 8 + 2] = gy; smf[r * 8 + 3] = gy;
        smf[r * 8 + 4] = gz; smf[r * 8 + 5] = gz;
        smf[r * 8 + 6] = h;  smf[r * 8 + 7] = h;
    }

    // 8 queries per thread: q_k = qb*QPB + tid + k*TPB, packed pairs (2j, 2j+1).
    int   qi[QPT];
    float hq[QPT];
    uint64_t nx2[4], ny2[4], nz2[4];
#pragma unroll
    for (int j = 0; j < 4; ++j) {
        int k0 = 2 * j, k1 = 2 * j + 1;
        int a = qb * QPB + tid + k0 * TPB;
        int c = qb * QPB + tid + k1 * TPB;
        qi[k0] = a; qi[k1] = c;
        int ac = a < N_ ? a : N_ - 1;
        int cc = c < N_ ? c : N_ - 1;
        float ax = qbase[ac * 3 + 0], ay = qbase[ac * 3 + 1], az = qbase[ac * 3 + 2];
        float bx = qbase[cc * 3 + 0], by = qbase[cc * 3 + 1], bz = qbase[cc * 3 + 2];
        hq[k0] = 0.5f * (ax * ax + ay * ay + az * az);
        hq[k1] = 0.5f * (bx * bx + by * by + bz * bz);
        asm("mov.b64 %0, {%1, %2};" : "=l"(nx2[j]) : "f"(-ax), "f"(-bx));
        asm("mov.b64 %0, {%1, %2};" : "=l"(ny2[j]) : "f"(-ay), "f"(-by));
        asm("mov.b64 %0, {%1, %2};" : "=l"(nz2[j]) : "f"(-az), "f"(-bz));
    }

    __syncthreads();

    uint32_t sbase = (uint32_t)__cvta_generic_to_shared(smf);

    float mn[QPT];
#pragma unroll
    for (int k = 0; k < QPT; ++k) mn[k] = 1.0e30f;

#pragma unroll 4
    for (int p = 0; p < RPAD; ++p) {
        uint64_t rx, ry, rz, rh;
        uint32_t a = sbase + p * 32;
        asm("ld.shared.v2.u64 {%0, %1}, [%2];" : "=l"(rx), "=l"(ry) : "r"(a));
        asm("ld.shared.v2.u64 {%0, %1}, [%2];" : "=l"(rz), "=l"(rh) : "r"(a + 16));
#pragma unroll
        for (int j = 0; j < 4; ++j) {
            // u = h - q.r for the two packed queries; unpack mov elided by ptxas.
            float u0, u1;
            asm("{\n\t"
                ".reg .b64 t;\n\t"
                "fma.rn.f32x2 t, %2, %3, %4;\n\t"
                "fma.rn.f32x2 t, %5, %6, t;\n\t"
                "fma.rn.f32x2 t, %7, %8, t;\n\t"
                "mov.b64 {%0, %1}, t;\n\t"
                "}"
                : "=f"(u0), "=f"(u1)
                : "l"(nz2[j]), "l"(rz), "l"(rh),
                  "l"(ny2[j]), "l"(ry),
                  "l"(nx2[j]), "l"(rx));
            mn[2 * j]     = fminf(mn[2 * j], u0);
            mn[2 * j + 1] = fminf(mn[2 * j + 1], u1);
        }
    }

    // Combine across ref chunks: atomicMax on complemented keys (min of v).
    const int base = (dir * B_ + b) * N_;
#pragma unroll
    for (int k = 0; k < QPT; ++k) {
        if (qi[k] < N_) {
            float v = 2.0f * (hq[k] + mn[k]);   // unclamped d2 for this chunk
            atomicMax(&g_min[base + qi[k]], f2key(v));
        }
    }
}

__global__ __launch_bounds__(1024) void chamfer_finish(float* __restrict__ out) {
    __shared__ float ssum[1024];
    const int tid = threadIdx.x;
    float acc = 0.0f;
    for (int i = tid; i < NQTOT; i += 1024) {
        unsigned int k = g_min[i];
        g_min[i] = 0u;                  // reset to identity for the next replay
        acc += fmaxf(key2f(k), 0.0f);
    }
    ssum[tid] = acc;
    __syncthreads();
    for (int off = 512; off > 0; off >>= 1) {
        if (tid < off) ssum[tid] += ssum[tid + off];
        __syncthreads();
    }
    if (tid == 0) out[0] = ssum[0] * (1.0f / (B_ * N_));
}

extern "C" void kernel_launch(void* const* d_in, const int* in_sizes, int n_in,
                              void* d_out, int out_size) {
    const float* pred = (const float*)d_in[0];
    const float* gt   = (const float*)d_in[1];
    dim3 grid(QB, 2 * B_, S_);
    chamfer_main<<<grid, TPB>>>(pred, gt);
    chamfer_finish<<<1, 1024>>>((float*)d_out);
}

// round 11
// speedup vs baseline: 1.1412x; 1.0463x over previous
#include <cuda_runtime.h>
#include <stdint.h>

// Bidirectional chamfer distance, B=4, N=M=5000, D=3.
// d2/2 = hq + hr - q.r. 8 queries/thread as 4 f32x2 packed pairs; refs
// broadcast from SMEM duplicated {x,x,y,y,z,z,h,h} -> ld.shared.v2.u64 gives
// aligned f32x2 operands. fma.rn.f32x2 + scalar FMNMX.
// Split-K combine via global atomicMax on COMPLEMENTED monotone float keys:
// identity = 0 == static zero-init, so no init kernel; finish resets entries
// as it consumes them. Finish is 40-block parallel with last-block final sum
// (fixed-order, deterministic).

#define B_    4
#define N_    5000
#define S_    40         // ref split (split-K over refs)
#define CHUNK 125        // N_/S_
#define TPB   128        // threads per block
#define QPT   8          // queries per thread
#define QPB   1024       // queries per block
#define QB    5          // ceil(5000/1024)
#define RPAD  128        // padded refs per chunk
#define NQTOT (2 * B_ * N_)   // 40000
#define FBLK  40         // finish blocks
#define FTPB  256        // finish threads per block
#define FPER  (NQTOT / FBLK)  // 1000 entries per finish block

// Per-(dir,b,q) running min, encoded so larger key == smaller value and key 0
// (static zero-init) is the identity (+huge).
__device__ unsigned int g_min[NQTOT];   // zero-initialized
__device__ float        g_bsums[FBLK];
__device__ unsigned int g_done;         // zero-initialized

__device__ __forceinline__ unsigned int f2key(float v) {
    unsigned int u = __float_as_uint(v);
    unsigned int m = (u & 0x80000000u) ? ~u : (u ^ 0x80000000u);
    return ~m;
}
__device__ __forceinline__ float key2f(unsigned int k) {
    unsigned int m = ~k;
    unsigned int u = (m & 0x80000000u) ? (m ^ 0x80000000u) : ~m;
    return __uint_as_float(u);
}

__global__ __launch_bounds__(TPB) void chamfer_main(const float* __restrict__ pred,
                                                    const float* __restrict__ gt) {
    __shared__ __align__(32) float smf[RPAD * 8];   // 4 KB

    const int qb  = blockIdx.x;          // query block 0..QB-1
    const int bd  = blockIdx.y;          // dir*B_ + b, 0..7
    const int s   = blockIdx.z;          // ref split 0..S_-1
    const int dir = bd >> 2;             // 0: pred->gt, 1: gt->pred
    const int b   = bd & 3;

    const float* __restrict__ qbase = (dir == 0 ? pred : gt) + b * N_ * 3;
    const float* __restrict__ rbase = (dir == 0 ? gt : pred) + b * N_ * 3 + s * CHUNK * 3;

    const int tid = threadIdx.x;

    // Cooperative load of the ref chunk, duplicated per point for f32x2 ops.
    for (int r = tid; r < RPAD; r += TPB) {
        float gx, gy, gz, h;
        if (r < CHUNK) {
            gx = rbase[r * 3 + 0];
            gy = rbase[r * 3 + 1];
            gz = rbase[r * 3 + 2];
            h  = 0.5f * (gx * gx + gy * gy + gz * gz);
        } else {
            gx = 0.0f; gy = 0.0f; gz = 0.0f; h = 1.0e30f;  // sentinel
        }
        smf[r * 8 + 0] = gx; smf[r * 8 + 1] = gx;
        smf[r * 8 + 2] = gy; smf[r * 8 + 3] = gy;
        smf[r * 8 + 4] = gz; smf[r * 8 + 5] = gz;
        smf[r * 8 + 6] = h;  smf[r * 8 + 7] = h;
    }

    // 8 queries per thread: q_k = qb*QPB + tid + k*TPB, packed pairs (2j, 2j+1).
    int   qi[QPT];
    float hq[QPT];
    uint64_t nx2[4], ny2[4], nz2[4];
#pragma unroll
    for (int j = 0; j < 4; ++j) {
        int k0 = 2 * j, k1 = 2 * j + 1;
        int a = qb * QPB + tid + k0 * TPB;
        int c = qb * QPB + tid + k1 * TPB;
        qi[k0] = a; qi[k1] = c;
        int ac = a < N_ ? a : N_ - 1;
        int cc = c < N_ ? c : N_ - 1;
        float ax = qbase[ac * 3 + 0], ay = qbase[ac * 3 + 1], az = qbase[ac * 3 + 2];
        float bx = qbase[cc * 3 + 0], by = qbase[cc * 3 + 1], bz = qbase[cc * 3 + 2];
        hq[k0] = 0.5f * (ax * ax + ay * ay + az * az);
        hq[k1] = 0.5f * (bx * bx + by * by + bz * bz);
        asm("mov.b64 %0, {%1, %2};" : "=l"(nx2[j]) : "f"(-ax), "f"(-bx));
        asm("mov.b64 %0, {%1, %2};" : "=l"(ny2[j]) : "f"(-ay), "f"(-by));
        asm("mov.b64 %0, {%1, %2};" : "=l"(nz2[j]) : "f"(-az), "f"(-bz));
    }

    __syncthreads();

    uint32_t sbase = (uint32_t)__cvta_generic_to_shared(smf);

    float mn[QPT];
#pragma unroll
    for (int k = 0; k < QPT; ++k) mn[k] = 1.0e30f;

#pragma unroll 4
    for (int p = 0; p < RPAD; ++p) {
        uint64_t rx, ry, rz, rh;
        uint32_t a = sbase + p * 32;
        asm("ld.shared.v2.u64 {%0, %1}, [%2];" : "=l"(rx), "=l"(ry) : "r"(a));
        asm("ld.shared.v2.u64 {%0, %1}, [%2];" : "=l"(rz), "=l"(rh) : "r"(a + 16));
#pragma unroll
        for (int j = 0; j < 4; ++j) {
            float u0, u1;
            asm("{\n\t"
                ".reg .b64 t;\n\t"
                "fma.rn.f32x2 t, %2, %3, %4;\n\t"
                "fma.rn.f32x2 t, %5, %6, t;\n\t"
                "fma.rn.f32x2 t, %7, %8, t;\n\t"
                "mov.b64 {%0, %1}, t;\n\t"
                "}"
                : "=f"(u0), "=f"(u1)
                : "l"(nz2[j]), "l"(rz), "l"(rh),
                  "l"(ny2[j]), "l"(ry),
                  "l"(nx2[j]), "l"(rx));
            mn[2 * j]     = fminf(mn[2 * j], u0);
            mn[2 * j + 1] = fminf(mn[2 * j + 1], u1);
        }
    }

    // Combine across ref chunks: atomicMax on complemented keys (min of v).
    const int base = (dir * B_ + b) * N_;
#pragma unroll
    for (int k = 0; k < QPT; ++k) {
        if (qi[k] < N_) {
            float v = 2.0f * (hq[k] + mn[k]);   // unclamped d2 for this chunk
            atomicMax(&g_min[base + qi[k]], f2key(v));
        }
    }
}

__global__ __launch_bounds__(FTPB) void chamfer_finish(float* __restrict__ out) {
    __shared__ float ssum[FTPB];
    __shared__ unsigned int s_ticket;
    const int tid = threadIdx.x;
    const int base = blockIdx.x * FPER;

    float acc = 0.0f;
    for (int i = tid; i < FPER; i += FTPB) {
        unsigned int k = g_min[base + i];
        g_min[base + i] = 0u;            // reset to identity for next replay
        acc += fmaxf(key2f(k), 0.0f);
    }
    ssum[tid] = acc;
    __syncthreads();
    for (int off = FTPB / 2; off > 0; off >>= 1) {
        if (tid < off) ssum[tid] += ssum[tid + off];
        __syncthreads();
    }
    if (tid == 0) {
        g_bsums[blockIdx.x] = ssum[0];
        __threadfence();
        s_ticket = atomicAdd(&g_done, 1u);
    }
    __syncthreads();
    if (s_ticket == FBLK - 1) {          // last block: deterministic final sum
        if (tid == 0) {
            __threadfence();
            volatile float* bs = g_bsums;
            float t = 0.0f;
#pragma unroll
            for (int i = 0; i < FBLK; ++i) t += bs[i];
            out[0] = t * (1.0f / (B_ * N_));
            g_done = 0u;                 // reset for next replay
        }
    }
}

extern "C" void kernel_launch(void* const* d_in, const int* in_sizes, int n_in,
                              void* d_out, int out_size) {
    const float* pred = (const float*)d_in[0];
    const float* gt   = (const float*)d_in[1];
    dim3 grid(QB, 2 * B_, S_);
    chamfer_main<<<grid, TPB>>>(pred, gt);
    chamfer_finish<<<FBLK, FTPB>>>((float*)d_out);
}